// round 14
// baseline (speedup 1.0000x reference)
#include <cuda_runtime.h>
#include <cuda_bf16.h>
#include <mma.h>

using namespace nvcuda;

#define N_NODES 50000
#define N_EDGES 800000
#define VOCABSZ 4096
#define EMB_DIM 128
#define H2 256      // 2*HIDDEN
#define HID 128
#define N_POS 1024

#define GRID_BUILD 740
#define EWB 256                      // EW-GEMM blocks (4096/16 tiles)
#define NWORK (GRID_BUILD - EWB)     // 484 worker blocks (barrier participants)
#define NT (NWORK * 256)             // 123904 worker threads

#define OUT_BLKS 16                  // classifier blocks
#define ZERO_BLKS 84                 // state-zeroing blocks appended to k_out

// ---------------- scratch (device globals; zero-initialized at module load) -
__device__ uint4 d_EWh[VOCABSZ * 32];       // emb @ W1 in bf16x2, 2 MB
__device__ int   d_dc[2 * N_NODES];         // interleaved {deg, cnt} per node
__device__ float d_coef[N_NODES];           // layer-2 edge weight per source node
__device__ unsigned char d_need[N_NODES];   // h1 needed at this node?
__device__ unsigned char d_sel[N_NODES];    // node in x_position? (stable in AB)
__device__ int   d_start[N_NODES];          // CSR start (unordered segments)
__device__ int   d_cursor[N_NODES];         // CSR fill cursor
__device__ int   d_list[N_NODES];           // compact list of needed nodes
__device__ int   d_nneed;
__device__ int   d_total;
__device__ int   d_csr1[N_EDGES];           // packed: (x[row]<<16) | bf16bits(w)
__device__ float d_svec[H2];
__device__ int   d_bar[8];                  // software barrier counters

__device__ __forceinline__ void red4(float4* p, float a, float b, float c, float d) {
    asm volatile("red.global.add.v4.f32 [%0], {%1,%2,%3,%4};"
                 :: "l"(p), "f"(a), "f"(b), "f"(c), "f"(d) : "memory");
}

__device__ __forceinline__ void acc8(float* a, uint4 q, float w) {
    float2 f0 = __bfloat1622float2(*(const __nv_bfloat162*)&q.x);
    float2 f1 = __bfloat1622float2(*(const __nv_bfloat162*)&q.y);
    float2 f2 = __bfloat1622float2(*(const __nv_bfloat162*)&q.z);
    float2 f3 = __bfloat1622float2(*(const __nv_bfloat162*)&q.w);
    a[0] += w * f0.x; a[1] += w * f0.y;
    a[2] += w * f1.x; a[3] += w * f1.y;
    a[4] += w * f2.x; a[5] += w * f2.y;
    a[6] += w * f3.x; a[7] += w * f3.y;
}

// worker-only global barrier (NWORK blocks; EW blocks never call this)
__device__ __forceinline__ void wbar(int i) {
    __syncthreads();
    if (threadIdx.x == 0) {
        __threadfence();
        atomicAdd(&d_bar[i], 1);
        while (*(volatile int*)&d_bar[i] < NWORK) __nanosleep(64);
    }
    __syncthreads();
}

__device__ __forceinline__ unsigned short f2bf(float w) {
    unsigned u = __float_as_uint(w);
    u += 0x7fffu + ((u >> 16) & 1u);   // round-to-nearest-even
    return (unsigned short)(u >> 16);
}

// ---------------- K0: wmma EW GEMM (blocks 0..255) + pipeline (256..739) ----
__global__ void __launch_bounds__(256, 5) k_build(
    const float* __restrict__ emb, const float* __restrict__ W1,
    const int* __restrict__ row, const int* __restrict__ col,
    const int* __restrict__ pos, const int* __restrict__ x)
{
    if (blockIdx.x < EWB) {
        // ---- EW GEMM: HMMA off smem-staged bf16 operands (9 KB smem) -------
        __shared__ __nv_bfloat16 sA[16 * 128];   // emb tile
        __shared__ __nv_bfloat16 sB[128 * 16];   // W1 N-chunk
        __shared__ float sCc[16 * 16];           // per-chunk result staging
        int t0 = blockIdx.x * 16;
        for (int i = threadIdx.x; i < 16 * 128; i += 256)
            sA[i] = __float2bfloat16(emb[t0 * 128 + i]);
        int w = threadIdx.x >> 5;
        int lane = threadIdx.x & 31;
        unsigned* EWu = (unsigned*)d_EWh;
        for (int c = 0; c < 16; c++) {
            // stage W1 columns [16c, 16c+16) as bf16 (cooperative, float2 loads)
            for (int i = threadIdx.x; i < 1024; i += 256) {
                int k = i >> 3, n2 = i & 7;
                float2 wv = *(const float2*)&W1[k * H2 + 16 * c + 2 * n2];
                *(__nv_bfloat162*)&sB[k * 16 + 2 * n2] = __floats2bfloat162_rn(wv.x, wv.y);
            }
            __syncthreads();   // sB ready (and sA on first iteration)
            if (w == (c & 7)) {
                wmma::fragment<wmma::matrix_a, 16, 16, 16, __nv_bfloat16, wmma::row_major> fa;
                wmma::fragment<wmma::matrix_b, 16, 16, 16, __nv_bfloat16, wmma::row_major> fb;
                wmma::fragment<wmma::accumulator, 16, 16, 16, float> fc;
                wmma::fill_fragment(fc, 0.f);
#pragma unroll
                for (int k = 0; k < 128; k += 16) {
                    wmma::load_matrix_sync(fa, sA + k, 128);
                    wmma::load_matrix_sync(fb, sB + k * 16, 16);
                    wmma::mma_sync(fc, fa, fb, fc);
                }
                wmma::store_matrix_sync(sCc, fc, 16, wmma::mem_row_major);
                __syncwarp();
                for (int i = lane; i < 128; i += 32) {
                    int r = i >> 3, p = i & 7;
                    __nv_bfloat162 h = __floats2bfloat162_rn(sCc[r * 16 + 2 * p],
                                                             sCc[r * 16 + 2 * p + 1]);
                    EWu[(t0 + r) * 128 + 8 * c + p] = *(unsigned*)&h;
                }
            }
            __syncthreads();   // pack done before sB is overwritten
        }
        return;
    }

    // ---- worker blocks (state arrives pre-zeroed from previous k_out) ------
    int wb = blockIdx.x - EWB;
    int gtid = wb * 256 + threadIdx.x;

    // stage P: cnt/sel/need from positions; zero svec for the coming gather
    if (gtid < N_POS) {
        int p = pos[gtid];
        atomicAdd(&d_dc[2 * p + 1], 1);
        d_need[p] = 1;
        d_sel[p] = 1;
    }
    if (gtid < H2) d_svec[gtid] = 0.f;
    wbar(0);

    // stage AB: ONE edge scan: degree atomics + need flags via sel[] (L1-hot)
    for (int i4 = gtid; i4 < N_EDGES / 4; i4 += NT) {
        int4 c = ((const int4*)col)[i4];
        int4 r = ((const int4*)row)[i4];
        atomicAdd(&d_dc[2 * c.x], 1);
        atomicAdd(&d_dc[2 * c.y], 1);
        atomicAdd(&d_dc[2 * c.z], 1);
        atomicAdd(&d_dc[2 * c.w], 1);
        if (d_sel[c.x]) d_need[r.x] = 1;
        if (d_sel[c.y]) d_need[r.y] = 1;
        if (d_sel[c.z]) d_need[r.z] = 1;
        if (d_sel[c.w]) d_need[r.w] = 1;
    }
    wbar(1);
    // --- from here on, deg/cnt/need are FINAL; no L1 line of them predates
    //     this barrier (AB used only atomics + sel), so plain loads are safe.

    // stage C: warp-aggregated CSR range allocation (NT >= N_NODES)
    {
        int u = gtid;
        int lane = threadIdx.x & 31;
        bool act = (u < N_NODES) && (d_need[u] != 0);
        int deg = act ? d_dc[2 * u] : 0;
        int pre = deg;
#pragma unroll
        for (int o = 1; o < 32; o <<= 1) {
            int v = __shfl_up_sync(0xffffffffu, pre, o);
            if (lane >= o) pre += v;
        }
        int wtot = __shfl_sync(0xffffffffu, pre, 31);
        int excl = pre - deg;
        unsigned m = __ballot_sync(0xffffffffu, act);
        int wcnt = __popc(m);
        int rank = __popc(m & ((1u << lane) - 1));
        int baseS = 0, baseL = 0;
        if (lane == 0 && wtot > 0) baseS = atomicAdd(&d_total, wtot);
        if (lane == 0 && wcnt > 0) baseL = atomicAdd(&d_nneed, wcnt);
        baseS = __shfl_sync(0xffffffffu, baseS, 0);
        baseL = __shfl_sync(0xffffffffu, baseL, 0);
        if (act) {
            int st = baseS + excl;
            d_start[u] = st;
            d_cursor[u] = st;
            d_list[baseL + rank] = u;
        }
    }
    wbar(2);

    // stage D: packed CSR build + coef accumulation (all reads L1-cacheable)
    for (int i4 = gtid; i4 < N_EDGES / 4; i4 += NT) {
        int4 c = ((const int4*)col)[i4];
        int4 r = ((const int4*)row)[i4];
#define DO_E(rr, cc) \
        if (d_need[cc]) { \
            int idx = atomicAdd(&d_cursor[cc], 1); \
            float w = rsqrtf((float)d_dc[2 * (rr)] + 1.f) * rsqrtf((float)d_dc[2 * (cc)] + 1.f); \
            d_csr1[idx] = (x[rr] << 16) | (int)f2bf(w); \
            int ct = d_dc[2 * (cc) + 1]; \
            if (ct > 0) atomicAdd(&d_coef[rr], w * (float)ct); \
        }
        DO_E(r.x, c.x) DO_E(r.y, c.y) DO_E(r.z, c.z) DO_E(r.w, c.w)
#undef DO_E
    }
}

// ---------------- K1: fused gather (bf16 EW): h1 + relu + layer-2 reduction -
__global__ void __launch_bounds__(256) k_gather(const float* __restrict__ b1,
                                                const int* __restrict__ x) {
    __shared__ float ssv[H2];
    int tid = threadIdx.x;
    ssv[tid] = 0.f;
    __syncthreads();
    int lane = tid & 31;
    int gw = (blockIdx.x * blockDim.x + tid) >> 5;
    int nw = (gridDim.x * blockDim.x) >> 5;
    int nn = d_nneed;
    float4 bq0 = ((const float4*)b1)[2 * lane];
    float4 bq1 = ((const float4*)b1)[2 * lane + 1];
    float sv[8];
#pragma unroll
    for (int k = 0; k < 8; k++) sv[k] = 0.f;
    for (int idx = gw; idx < nn; idx += nw) {
        int u = d_list[idx];
        int2 dcu = *(const int2*)&d_dc[2 * u];
        float du = rsqrtf((float)dcu.x + 1.f);
        float d2 = du * du;
        int toku = x[u];
        float a[8];
#pragma unroll
        for (int k = 0; k < 8; k++) a[k] = 0.f;
        acc8(a, d_EWh[(size_t)toku * 32 + lane], d2);
        int s0 = d_start[u], len = dcu.x;
        for (int b = 0; b < len; b += 32) {
            int i = b + lane;
            int ev = (i < len) ? d_csr1[s0 + i] : 0;   // 0 => w = +0.0f
            int n4 = (min(32, len - b) + 3) & ~3;
            for (int j = 0; j < n4; j += 4) {
                int e0 = __shfl_sync(0xffffffffu, ev, j + 0);
                int e1 = __shfl_sync(0xffffffffu, ev, j + 1);
                int e2 = __shfl_sync(0xffffffffu, ev, j + 2);
                int e3 = __shfl_sync(0xffffffffu, ev, j + 3);
                uint4 q0 = d_EWh[(size_t)((unsigned)e0 >> 16) * 32 + lane];
                uint4 q1 = d_EWh[(size_t)((unsigned)e1 >> 16) * 32 + lane];
                uint4 q2 = d_EWh[(size_t)((unsigned)e2 >> 16) * 32 + lane];
                uint4 q3 = d_EWh[(size_t)((unsigned)e3 >> 16) * 32 + lane];
                acc8(a, q0, __uint_as_float((unsigned)e0 << 16));
                acc8(a, q1, __uint_as_float((unsigned)e1 << 16));
                acc8(a, q2, __uint_as_float((unsigned)e2 << 16));
                acc8(a, q3, __uint_as_float((unsigned)e3 << 16));
            }
        }
        float ct = d_coef[u] + (float)dcu.y * d2;
        sv[0] += ct * fmaxf(a[0] + bq0.x, 0.f);
        sv[1] += ct * fmaxf(a[1] + bq0.y, 0.f);
        sv[2] += ct * fmaxf(a[2] + bq0.z, 0.f);
        sv[3] += ct * fmaxf(a[3] + bq0.w, 0.f);
        sv[4] += ct * fmaxf(a[4] + bq1.x, 0.f);
        sv[5] += ct * fmaxf(a[5] + bq1.y, 0.f);
        sv[6] += ct * fmaxf(a[6] + bq1.z, 0.f);
        sv[7] += ct * fmaxf(a[7] + bq1.w, 0.f);
    }
#pragma unroll
    for (int k = 0; k < 8; k++) atomicAdd(&ssv[8 * lane + k], sv[k]);
    __syncthreads();
    if (tid < 64) {
        float4 p = ((float4*)ssv)[tid];
        red4(((float4*)d_svec) + tid, p.x, p.y, p.z, p.w);
    }
}

// ---------------- K2: classifier (blocks 0..15) + state zeroing (16..99) ----
__global__ void __launch_bounds__(256) k_out(const float* __restrict__ W2,
                                             const float* __restrict__ b2,
                                             const float* __restrict__ Wc,
                                             const float* __restrict__ bc,
                                             float* __restrict__ out) {
    if (blockIdx.x < OUT_BLKS) {
        __shared__ float zb[HID];
        int t = threadIdx.x;
        if (t < HID) {
            float acc = 0.f;
            for (int k = 0; k < H2; k++) acc += d_svec[k] * W2[k * HID + t];
            zb[t] = acc * (1.0f / (float)N_POS) + b2[t];
        }
        __syncthreads();
        int c = blockIdx.x * 256 + t;
        float acc = bc[c];
#pragma unroll 8
        for (int j = 0; j < HID; j++) acc += zb[j] * Wc[j * VOCABSZ + c];
        out[c] = acc;
    } else {
        // zero per-frame state for the NEXT replay (invariant: zero on entry)
        int zt = (blockIdx.x - OUT_BLKS) * 256 + threadIdx.x;
        int nz = ZERO_BLKS * 256;
        for (int i = zt; i < N_NODES; i += nz) {
            d_dc[2 * i] = 0; d_dc[2 * i + 1] = 0;
            d_coef[i] = 0.f; d_need[i] = 0; d_sel[i] = 0;
        }
        if (zt == 0) { d_total = 0; d_nneed = 0; }
        if (zt < 8) d_bar[zt] = 0;
    }
}

extern "C" void kernel_launch(void* const* d_in, const int* in_sizes, int n_in,
                              void* d_out, int out_size) {
    const int*   x    = (const int*)d_in[0];
    const int*   ei   = (const int*)d_in[1];
    const int*   pos  = (const int*)d_in[2];
    const float* emb  = (const float*)d_in[3];
    const float* W1   = (const float*)d_in[4];
    const float* b1   = (const float*)d_in[5];
    const float* W2   = (const float*)d_in[6];
    const float* b2   = (const float*)d_in[7];
    const float* Wc   = (const float*)d_in[8];
    const float* bc   = (const float*)d_in[9];
    float* out = (float*)d_out;
    const int* row = ei;
    const int* col = ei + N_EDGES;

    k_build<<<GRID_BUILD, 256>>>(emb, W1, row, col, pos, x);
    k_gather<<<1184, 256>>>(b1, x);
    k_out<<<OUT_BLKS + ZERO_BLKS, 256>>>(W2, b2, Wc, bc, out);
}

// round 15
// speedup vs baseline: 1.1007x; 1.1007x over previous
#include <cuda_runtime.h>
#include <cuda_bf16.h>

#define N_NODES 50000
#define N_EDGES 800000
#define VOCABSZ 4096
#define EMB_DIM 128
#define H2 256      // 2*HIDDEN
#define HID 128
#define N_POS 1024

#define GRID_BUILD 740
#define EWB 256                      // EW-GEMM blocks (4096/16 tiles)
#define NWORK (GRID_BUILD - EWB)     // 484 worker blocks
#define NT (NWORK * 256)             // 123904 worker threads

#define OUT_BLKS 16                  // classifier blocks
#define ZERO_BLKS 84                 // state-zeroing blocks appended to k_out

// ---------------- scratch (device globals; zero-initialized at module load) -
__device__ uint4 d_EWh[VOCABSZ * 32];       // emb @ W1 in bf16x2, 2 MB
__device__ int   d_dc[2 * N_NODES];         // interleaved {deg, cnt} per node
__device__ float d_coef[N_NODES];           // layer-2 edge weight per source node
__device__ unsigned char d_need[N_NODES];   // h1 needed at this node?
__device__ unsigned char d_sel[N_NODES];    // node in x_position? (stable in AB)
__device__ int   d_start[N_NODES];          // CSR start (unordered segments)
__device__ int   d_cursor[N_NODES];         // CSR fill cursor
__device__ int   d_list[N_NODES];           // compact list of needed nodes
__device__ int   d_nneed;
__device__ int   d_total;
__device__ int   d_csr1[N_EDGES];           // packed: (x[row]<<16) | bf16bits(w)
__device__ float d_svec[H2];
__device__ int   d_bar[8];                  // software barrier counters

__device__ __forceinline__ void red4(float4* p, float a, float b, float c, float d) {
    asm volatile("red.global.add.v4.f32 [%0], {%1,%2,%3,%4};"
                 :: "l"(p), "f"(a), "f"(b), "f"(c), "f"(d) : "memory");
}

__device__ __forceinline__ void acc8(float* a, uint4 q, float w) {
    float2 f0 = __bfloat1622float2(*(const __nv_bfloat162*)&q.x);
    float2 f1 = __bfloat1622float2(*(const __nv_bfloat162*)&q.y);
    float2 f2 = __bfloat1622float2(*(const __nv_bfloat162*)&q.z);
    float2 f3 = __bfloat1622float2(*(const __nv_bfloat162*)&q.w);
    a[0] += w * f0.x; a[1] += w * f0.y;
    a[2] += w * f1.x; a[3] += w * f1.y;
    a[4] += w * f2.x; a[5] += w * f2.y;
    a[6] += w * f3.x; a[7] += w * f3.y;
}

// global barrier with configurable population
__device__ __forceinline__ void gbar(int i, int target) {
    __syncthreads();
    if (threadIdx.x == 0) {
        __threadfence();
        atomicAdd(&d_bar[i], 1);
        while (*(volatile int*)&d_bar[i] < target) __nanosleep(64);
    }
    __syncthreads();
}

__device__ __forceinline__ unsigned short f2bf(float w) {
    unsigned u = __float_as_uint(w);
    u += 0x7fffu + ((u >> 16) & 1u);   // round-to-nearest-even
    return (unsigned short)(u >> 16);
}

// ---------------- K0: build + EW GEMM + fused gather ------------------------
__global__ void __launch_bounds__(256, 5) k_build(
    const float* __restrict__ emb, const float* __restrict__ W1,
    const int* __restrict__ row, const int* __restrict__ col,
    const int* __restrict__ pos, const int* __restrict__ x,
    const float* __restrict__ b1)
{
    __shared__ float se_t[128 * 16];   // transposed emb tile (EW blocks)
    __shared__ float ssv[H2];          // gather-stage reduction buffer

    if (blockIdx.x < EWB) {
        // ---- EW GEMM: scalar FFMA, transposed smem tile (LDS.128 reads) ----
        int t0 = blockIdx.x * 16;
        for (int i = threadIdx.x; i < 16 * 128; i += 256) {
            int r = i >> 7, k = i & 127;
            se_t[k * 16 + r] = emb[t0 * 128 + i];
        }
        __syncthreads();
        int j = threadIdx.x;
        const float4* se4 = (const float4*)se_t;
        float acc[16];
#pragma unroll
        for (int r = 0; r < 16; r++) acc[r] = 0.f;
        for (int k = 0; k < 128; k++) {
            float w = W1[k * H2 + j];
            float4 a0 = se4[k * 4 + 0];
            float4 a1 = se4[k * 4 + 1];
            float4 a2 = se4[k * 4 + 2];
            float4 a3 = se4[k * 4 + 3];
            acc[0] += a0.x * w;  acc[1] += a0.y * w;  acc[2] += a0.z * w;  acc[3] += a0.w * w;
            acc[4] += a1.x * w;  acc[5] += a1.y * w;  acc[6] += a1.z * w;  acc[7] += a1.w * w;
            acc[8] += a2.x * w;  acc[9] += a2.y * w;  acc[10] += a2.z * w; acc[11] += a2.w * w;
            acc[12] += a3.x * w; acc[13] += a3.y * w; acc[14] += a3.z * w; acc[15] += a3.w * w;
        }
        unsigned* EWu = (unsigned*)d_EWh;
#pragma unroll
        for (int r = 0; r < 16; r++) {
            float v = acc[r];
            float vh = __shfl_down_sync(0xffffffffu, v, 1);
            if ((j & 1) == 0) {
                __nv_bfloat162 h = __floats2bfloat162_rn(v, vh);
                EWu[(t0 + r) * 128 + (j >> 1)] = *(unsigned*)&h;
            }
        }
        // EW done — join the all-blocks barrier before the gather stage
        gbar(3, GRID_BUILD);
    } else {
        // ---- worker blocks (state arrives pre-zeroed from previous k_out) --
        int wb = blockIdx.x - EWB;
        int gtid = wb * 256 + threadIdx.x;

        // stage P: cnt/sel/need from positions; zero svec for the gather
        if (gtid < N_POS) {
            int p = pos[gtid];
            atomicAdd(&d_dc[2 * p + 1], 1);
            d_need[p] = 1;
            d_sel[p] = 1;
        }
        if (gtid < H2) d_svec[gtid] = 0.f;
        gbar(0, NWORK);

        // stage AB: ONE edge scan: degree atomics + need flags via sel[]
        for (int i4 = gtid; i4 < N_EDGES / 4; i4 += NT) {
            int4 c = ((const int4*)col)[i4];
            int4 r = ((const int4*)row)[i4];
            atomicAdd(&d_dc[2 * c.x], 1);
            atomicAdd(&d_dc[2 * c.y], 1);
            atomicAdd(&d_dc[2 * c.z], 1);
            atomicAdd(&d_dc[2 * c.w], 1);
            if (d_sel[c.x]) d_need[r.x] = 1;
            if (d_sel[c.y]) d_need[r.y] = 1;
            if (d_sel[c.z]) d_need[r.z] = 1;
            if (d_sel[c.w]) d_need[r.w] = 1;
        }
        gbar(1, NWORK);
        // deg/cnt/need FINAL from here; no stale L1 lines possible (AB used
        // only atomics + sel), so plain loads are safe.

        // stage C: warp-aggregated CSR range allocation (NT >= N_NODES)
        {
            int u = gtid;
            int lane = threadIdx.x & 31;
            bool act = (u < N_NODES) && (d_need[u] != 0);
            int deg = act ? d_dc[2 * u] : 0;
            int pre = deg;
#pragma unroll
            for (int o = 1; o < 32; o <<= 1) {
                int v = __shfl_up_sync(0xffffffffu, pre, o);
                if (lane >= o) pre += v;
            }
            int wtot = __shfl_sync(0xffffffffu, pre, 31);
            int excl = pre - deg;
            unsigned m = __ballot_sync(0xffffffffu, act);
            int wcnt = __popc(m);
            int rank = __popc(m & ((1u << lane) - 1));
            int baseS = 0, baseL = 0;
            if (lane == 0 && wtot > 0) baseS = atomicAdd(&d_total, wtot);
            if (lane == 0 && wcnt > 0) baseL = atomicAdd(&d_nneed, wcnt);
            baseS = __shfl_sync(0xffffffffu, baseS, 0);
            baseL = __shfl_sync(0xffffffffu, baseL, 0);
            if (act) {
                int st = baseS + excl;
                d_start[u] = st;
                d_cursor[u] = st;
                d_list[baseL + rank] = u;
            }
        }
        gbar(2, NWORK);

        // stage D: packed CSR build + coef accumulation
        for (int i4 = gtid; i4 < N_EDGES / 4; i4 += NT) {
            int4 c = ((const int4*)col)[i4];
            int4 r = ((const int4*)row)[i4];
#define DO_E(rr, cc) \
            if (d_need[cc]) { \
                int idx = atomicAdd(&d_cursor[cc], 1); \
                float w = rsqrtf((float)d_dc[2 * (rr)] + 1.f) * rsqrtf((float)d_dc[2 * (cc)] + 1.f); \
                d_csr1[idx] = (x[rr] << 16) | (int)f2bf(w); \
                int ct = d_dc[2 * (cc) + 1]; \
                if (ct > 0) atomicAdd(&d_coef[rr], w * (float)ct); \
            }
            DO_E(r.x, c.x) DO_E(r.y, c.y) DO_E(r.z, c.z) DO_E(r.w, c.w)
#undef DO_E
        }
        gbar(3, GRID_BUILD);
    }

    // ================= stage E: fused gather (ALL 740 blocks) ===============
    {
        int tid = threadIdx.x;
        ssv[tid] = 0.f;
        __syncthreads();
        int lane = tid & 31;
        int gw = (blockIdx.x * 256 + tid) >> 5;
        int nw = (GRID_BUILD * 256) >> 5;
        int nn = __ldcg(&d_nneed);
        float4 bq0 = ((const float4*)b1)[2 * lane];
        float4 bq1 = ((const float4*)b1)[2 * lane + 1];
        float sv[8];
#pragma unroll
        for (int k = 0; k < 8; k++) sv[k] = 0.f;
        for (int idx = gw; idx < nn; idx += nw) {
            int u = d_list[idx];
            int2 dcu = *(const int2*)&d_dc[2 * u];
            float du = rsqrtf((float)dcu.x + 1.f);
            float d2 = du * du;
            int toku = x[u];
            float a[8];
#pragma unroll
            for (int k = 0; k < 8; k++) a[k] = 0.f;
            acc8(a, d_EWh[(size_t)toku * 32 + lane], d2);
            int s0 = d_start[u], len = dcu.x;
            for (int b = 0; b < len; b += 32) {
                int i = b + lane;
                int ev = (i < len) ? d_csr1[s0 + i] : 0;   // 0 => w = +0.0f
                int n4 = (min(32, len - b) + 3) & ~3;
                for (int j = 0; j < n4; j += 4) {
                    int e0 = __shfl_sync(0xffffffffu, ev, j + 0);
                    int e1 = __shfl_sync(0xffffffffu, ev, j + 1);
                    int e2 = __shfl_sync(0xffffffffu, ev, j + 2);
                    int e3 = __shfl_sync(0xffffffffu, ev, j + 3);
                    uint4 q0 = d_EWh[(size_t)((unsigned)e0 >> 16) * 32 + lane];
                    uint4 q1 = d_EWh[(size_t)((unsigned)e1 >> 16) * 32 + lane];
                    uint4 q2 = d_EWh[(size_t)((unsigned)e2 >> 16) * 32 + lane];
                    uint4 q3 = d_EWh[(size_t)((unsigned)e3 >> 16) * 32 + lane];
                    acc8(a, q0, __uint_as_float((unsigned)e0 << 16));
                    acc8(a, q1, __uint_as_float((unsigned)e1 << 16));
                    acc8(a, q2, __uint_as_float((unsigned)e2 << 16));
                    acc8(a, q3, __uint_as_float((unsigned)e3 << 16));
                }
            }
            float ct = d_coef[u] + (float)dcu.y * d2;
            sv[0] += ct * fmaxf(a[0] + bq0.x, 0.f);
            sv[1] += ct * fmaxf(a[1] + bq0.y, 0.f);
            sv[2] += ct * fmaxf(a[2] + bq0.z, 0.f);
            sv[3] += ct * fmaxf(a[3] + bq0.w, 0.f);
            sv[4] += ct * fmaxf(a[4] + bq1.x, 0.f);
            sv[5] += ct * fmaxf(a[5] + bq1.y, 0.f);
            sv[6] += ct * fmaxf(a[6] + bq1.z, 0.f);
            sv[7] += ct * fmaxf(a[7] + bq1.w, 0.f);
        }
#pragma unroll
        for (int k = 0; k < 8; k++) atomicAdd(&ssv[8 * lane + k], sv[k]);
        __syncthreads();
        if (tid < 64) {
            float4 p = ((float4*)ssv)[tid];
            red4(((float4*)d_svec) + tid, p.x, p.y, p.z, p.w);
        }
    }
}

// ---------------- K1: classifier (blocks 0..15) + state zeroing (16..99) ----
__global__ void __launch_bounds__(256) k_out(const float* __restrict__ W2,
                                             const float* __restrict__ b2,
                                             const float* __restrict__ Wc,
                                             const float* __restrict__ bc,
                                             float* __restrict__ out) {
    if (blockIdx.x < OUT_BLKS) {
        __shared__ float zb[HID];
        int t = threadIdx.x;
        if (t < HID) {
            float acc = 0.f;
            for (int k = 0; k < H2; k++) acc += d_svec[k] * W2[k * HID + t];
            zb[t] = acc * (1.0f / (float)N_POS) + b2[t];
        }
        __syncthreads();
        int c = blockIdx.x * 256 + t;
        float acc = bc[c];
#pragma unroll 8
        for (int j = 0; j < HID; j++) acc += zb[j] * Wc[j * VOCABSZ + c];
        out[c] = acc;
    } else {
        // zero per-frame state for the NEXT replay (invariant: zero on entry)
        int zt = (blockIdx.x - OUT_BLKS) * 256 + threadIdx.x;
        int nz = ZERO_BLKS * 256;
        for (int i = zt; i < N_NODES; i += nz) {
            d_dc[2 * i] = 0; d_dc[2 * i + 1] = 0;
            d_coef[i] = 0.f; d_need[i] = 0; d_sel[i] = 0;
        }
        if (zt == 0) { d_total = 0; d_nneed = 0; }
        if (zt < 8) d_bar[zt] = 0;
    }
}

extern "C" void kernel_launch(void* const* d_in, const int* in_sizes, int n_in,
                              void* d_out, int out_size) {
    const int*   x    = (const int*)d_in[0];
    const int*   ei   = (const int*)d_in[1];
    const int*   pos  = (const int*)d_in[2];
    const float* emb  = (const float*)d_in[3];
    const float* W1   = (const float*)d_in[4];
    const float* b1   = (const float*)d_in[5];
    const float* W2   = (const float*)d_in[6];
    const float* b2   = (const float*)d_in[7];
    const float* Wc   = (const float*)d_in[8];
    const float* bc   = (const float*)d_in[9];
    float* out = (float*)d_out;
    const int* row = ei;
    const int* col = ei + N_EDGES;

    k_build<<<GRID_BUILD, 256>>>(emb, W1, row, col, pos, x, b1);
    k_out<<<OUT_BLKS + ZERO_BLKS, 256>>>(W2, b2, Wc, bc, out);
}

// round 16
// speedup vs baseline: 1.1746x; 1.0671x over previous
#include <cuda_runtime.h>
#include <cuda_bf16.h>

#define N_NODES 50000
#define N_EDGES 800000
#define VOCABSZ 4096
#define EMB_DIM 128
#define H2 256      // 2*HIDDEN
#define HID 128
#define N_POS 1024

#define GRID_BUILD 740
#define EWB 256                      // EW-GEMM blocks (4096/16 tiles)
#define NWORK (GRID_BUILD - EWB)     // 484 worker blocks
#define NT (NWORK * 256)             // 123904 worker threads

#define OUT_BLKS 64                  // classifier blocks (64 vocab cols each)
#define ZERO_BLKS 84                 // state-zeroing blocks appended to k_out

// ---------------- scratch (device globals; zero-initialized at module load) -
__device__ uint4 d_EWh[VOCABSZ * 32];       // emb @ W1 in bf16x2, 2 MB
__device__ int   d_dc[2 * N_NODES];         // interleaved {deg, cnt} per node
__device__ float d_coef[N_NODES];           // layer-2 edge weight per source node
__device__ unsigned char d_need[N_NODES];   // h1 needed at this node?
__device__ unsigned char d_sel[N_NODES];    // node in x_position? (stable in AB)
__device__ int   d_start[N_NODES];          // CSR start (unordered segments)
__device__ int   d_cursor[N_NODES];         // CSR fill cursor
__device__ int   d_list[N_NODES];           // compact list of needed nodes
__device__ int   d_nneed;
__device__ int   d_total;
__device__ int   d_csr1[N_EDGES];           // packed: (x[row]<<16) | bf16bits(w)
__device__ float d_svec[H2];
__device__ int   d_bar[8];                  // software barrier counters

__device__ __forceinline__ void red4(float4* p, float a, float b, float c, float d) {
    asm volatile("red.global.add.v4.f32 [%0], {%1,%2,%3,%4};"
                 :: "l"(p), "f"(a), "f"(b), "f"(c), "f"(d) : "memory");
}

__device__ __forceinline__ void acc8(float* a, uint4 q, float w) {
    float2 f0 = __bfloat1622float2(*(const __nv_bfloat162*)&q.x);
    float2 f1 = __bfloat1622float2(*(const __nv_bfloat162*)&q.y);
    float2 f2 = __bfloat1622float2(*(const __nv_bfloat162*)&q.z);
    float2 f3 = __bfloat1622float2(*(const __nv_bfloat162*)&q.w);
    a[0] += w * f0.x; a[1] += w * f0.y;
    a[2] += w * f1.x; a[3] += w * f1.y;
    a[4] += w * f2.x; a[5] += w * f2.y;
    a[6] += w * f3.x; a[7] += w * f3.y;
}

// global barrier with configurable population
__device__ __forceinline__ void gbar(int i, int target) {
    __syncthreads();
    if (threadIdx.x == 0) {
        __threadfence();
        atomicAdd(&d_bar[i], 1);
        while (*(volatile int*)&d_bar[i] < target) __nanosleep(64);
    }
    __syncthreads();
}

__device__ __forceinline__ unsigned short f2bf(float w) {
    unsigned u = __float_as_uint(w);
    u += 0x7fffu + ((u >> 16) & 1u);   // round-to-nearest-even
    return (unsigned short)(u >> 16);
}

// ---------------- K0: build + EW GEMM + fused gather ------------------------
__global__ void __launch_bounds__(256, 5) k_build(
    const float* __restrict__ emb, const float* __restrict__ W1,
    const int* __restrict__ row, const int* __restrict__ col,
    const int* __restrict__ pos, const int* __restrict__ x,
    const float* __restrict__ b1)
{
    __shared__ float se_t[128 * 16];   // transposed emb tile (EW blocks)
    __shared__ float ssv[H2];          // gather-stage reduction buffer

    if (blockIdx.x < EWB) {
        // ---- EW GEMM: scalar FFMA, transposed smem tile (LDS.128 reads) ----
        int t0 = blockIdx.x * 16;
        for (int i = threadIdx.x; i < 16 * 128; i += 256) {
            int r = i >> 7, k = i & 127;
            se_t[k * 16 + r] = emb[t0 * 128 + i];
        }
        __syncthreads();
        int j = threadIdx.x;
        const float4* se4 = (const float4*)se_t;
        float acc[16];
#pragma unroll
        for (int r = 0; r < 16; r++) acc[r] = 0.f;
        for (int k = 0; k < 128; k++) {
            float w = W1[k * H2 + j];
            float4 a0 = se4[k * 4 + 0];
            float4 a1 = se4[k * 4 + 1];
            float4 a2 = se4[k * 4 + 2];
            float4 a3 = se4[k * 4 + 3];
            acc[0] += a0.x * w;  acc[1] += a0.y * w;  acc[2] += a0.z * w;  acc[3] += a0.w * w;
            acc[4] += a1.x * w;  acc[5] += a1.y * w;  acc[6] += a1.z * w;  acc[7] += a1.w * w;
            acc[8] += a2.x * w;  acc[9] += a2.y * w;  acc[10] += a2.z * w; acc[11] += a2.w * w;
            acc[12] += a3.x * w; acc[13] += a3.y * w; acc[14] += a3.z * w; acc[15] += a3.w * w;
        }
        unsigned* EWu = (unsigned*)d_EWh;
#pragma unroll
        for (int r = 0; r < 16; r++) {
            float v = acc[r];
            float vh = __shfl_down_sync(0xffffffffu, v, 1);
            if ((j & 1) == 0) {
                __nv_bfloat162 h = __floats2bfloat162_rn(v, vh);
                EWu[(t0 + r) * 128 + (j >> 1)] = *(unsigned*)&h;
            }
        }
        // EW done — join the all-blocks barrier before the gather stage
        gbar(3, GRID_BUILD);
    } else {
        // ---- worker blocks (state arrives pre-zeroed from previous k_out) --
        int wb = blockIdx.x - EWB;
        int gtid = wb * 256 + threadIdx.x;

        // stage P: cnt/sel/need from positions; zero svec for the gather
        if (gtid < N_POS) {
            int p = pos[gtid];
            atomicAdd(&d_dc[2 * p + 1], 1);
            d_need[p] = 1;
            d_sel[p] = 1;
        }
        if (gtid < H2) d_svec[gtid] = 0.f;
        gbar(0, NWORK);

        // stage AB: ONE edge scan: degree atomics + need flags via sel[]
        for (int i4 = gtid; i4 < N_EDGES / 4; i4 += NT) {
            int4 c = ((const int4*)col)[i4];
            int4 r = ((const int4*)row)[i4];
            atomicAdd(&d_dc[2 * c.x], 1);
            atomicAdd(&d_dc[2 * c.y], 1);
            atomicAdd(&d_dc[2 * c.z], 1);
            atomicAdd(&d_dc[2 * c.w], 1);
            if (d_sel[c.x]) d_need[r.x] = 1;
            if (d_sel[c.y]) d_need[r.y] = 1;
            if (d_sel[c.z]) d_need[r.z] = 1;
            if (d_sel[c.w]) d_need[r.w] = 1;
        }
        gbar(1, NWORK);
        // deg/cnt/need FINAL from here; no stale L1 lines possible.

        // stage C: warp-aggregated CSR range allocation (NT >= N_NODES)
        {
            int u = gtid;
            int lane = threadIdx.x & 31;
            bool act = (u < N_NODES) && (d_need[u] != 0);
            int deg = act ? d_dc[2 * u] : 0;
            int pre = deg;
#pragma unroll
            for (int o = 1; o < 32; o <<= 1) {
                int v = __shfl_up_sync(0xffffffffu, pre, o);
                if (lane >= o) pre += v;
            }
            int wtot = __shfl_sync(0xffffffffu, pre, 31);
            int excl = pre - deg;
            unsigned m = __ballot_sync(0xffffffffu, act);
            int wcnt = __popc(m);
            int rank = __popc(m & ((1u << lane) - 1));
            int baseS = 0, baseL = 0;
            if (lane == 0 && wtot > 0) baseS = atomicAdd(&d_total, wtot);
            if (lane == 0 && wcnt > 0) baseL = atomicAdd(&d_nneed, wcnt);
            baseS = __shfl_sync(0xffffffffu, baseS, 0);
            baseL = __shfl_sync(0xffffffffu, baseL, 0);
            if (act) {
                int st = baseS + excl;
                d_start[u] = st;
                d_cursor[u] = st;
                d_list[baseL + rank] = u;
            }
        }
        gbar(2, NWORK);

        // stage D: packed CSR build + coef accumulation
        for (int i4 = gtid; i4 < N_EDGES / 4; i4 += NT) {
            int4 c = ((const int4*)col)[i4];
            int4 r = ((const int4*)row)[i4];
#define DO_E(rr, cc) \
            if (d_need[cc]) { \
                int idx = atomicAdd(&d_cursor[cc], 1); \
                float w = rsqrtf((float)d_dc[2 * (rr)] + 1.f) * rsqrtf((float)d_dc[2 * (cc)] + 1.f); \
                d_csr1[idx] = (x[rr] << 16) | (int)f2bf(w); \
                int ct = d_dc[2 * (cc) + 1]; \
                if (ct > 0) atomicAdd(&d_coef[rr], w * (float)ct); \
            }
            DO_E(r.x, c.x) DO_E(r.y, c.y) DO_E(r.z, c.z) DO_E(r.w, c.w)
#undef DO_E
        }
        gbar(3, GRID_BUILD);
    }

    // ================= stage E: fused gather (ALL 740 blocks) ===============
    {
        int tid = threadIdx.x;
        ssv[tid] = 0.f;
        __syncthreads();
        int lane = tid & 31;
        int gw = (blockIdx.x * 256 + tid) >> 5;
        int nw = (GRID_BUILD * 256) >> 5;
        int nn = __ldcg(&d_nneed);
        float4 bq0 = ((const float4*)b1)[2 * lane];
        float4 bq1 = ((const float4*)b1)[2 * lane + 1];
        float sv[8];
#pragma unroll
        for (int k = 0; k < 8; k++) sv[k] = 0.f;
        for (int idx = gw; idx < nn; idx += nw) {
            int u = d_list[idx];
            int2 dcu = *(const int2*)&d_dc[2 * u];
            float du = rsqrtf((float)dcu.x + 1.f);
            float d2 = du * du;
            int toku = x[u];
            float a[8];
#pragma unroll
            for (int k = 0; k < 8; k++) a[k] = 0.f;
            acc8(a, d_EWh[(size_t)toku * 32 + lane], d2);
            int s0 = d_start[u], len = dcu.x;
            for (int b = 0; b < len; b += 32) {
                int i = b + lane;
                int ev = (i < len) ? d_csr1[s0 + i] : 0;   // 0 => w = +0.0f
                int n4 = (min(32, len - b) + 3) & ~3;
                for (int j = 0; j < n4; j += 4) {
                    int e0 = __shfl_sync(0xffffffffu, ev, j + 0);
                    int e1 = __shfl_sync(0xffffffffu, ev, j + 1);
                    int e2 = __shfl_sync(0xffffffffu, ev, j + 2);
                    int e3 = __shfl_sync(0xffffffffu, ev, j + 3);
                    uint4 q0 = d_EWh[(size_t)((unsigned)e0 >> 16) * 32 + lane];
                    uint4 q1 = d_EWh[(size_t)((unsigned)e1 >> 16) * 32 + lane];
                    uint4 q2 = d_EWh[(size_t)((unsigned)e2 >> 16) * 32 + lane];
                    uint4 q3 = d_EWh[(size_t)((unsigned)e3 >> 16) * 32 + lane];
                    acc8(a, q0, __uint_as_float((unsigned)e0 << 16));
                    acc8(a, q1, __uint_as_float((unsigned)e1 << 16));
                    acc8(a, q2, __uint_as_float((unsigned)e2 << 16));
                    acc8(a, q3, __uint_as_float((unsigned)e3 << 16));
                }
            }
            float ct = d_coef[u] + (float)dcu.y * d2;
            sv[0] += ct * fmaxf(a[0] + bq0.x, 0.f);
            sv[1] += ct * fmaxf(a[1] + bq0.y, 0.f);
            sv[2] += ct * fmaxf(a[2] + bq0.z, 0.f);
            sv[3] += ct * fmaxf(a[3] + bq0.w, 0.f);
            sv[4] += ct * fmaxf(a[4] + bq1.x, 0.f);
            sv[5] += ct * fmaxf(a[5] + bq1.y, 0.f);
            sv[6] += ct * fmaxf(a[6] + bq1.z, 0.f);
            sv[7] += ct * fmaxf(a[7] + bq1.w, 0.f);
        }
#pragma unroll
        for (int k = 0; k < 8; k++) atomicAdd(&ssv[8 * lane + k], sv[k]);
        __syncthreads();
        if (tid < 64) {
            float4 p = ((float4*)ssv)[tid];
            red4(((float4*)d_svec) + tid, p.x, p.y, p.z, p.w);
        }
    }
}

// ---------------- K1: classifier (blocks 0..63) + state zeroing (64..147) ---
__global__ void __launch_bounds__(256) k_out(const float* __restrict__ W2,
                                             const float* __restrict__ b2,
                                             const float* __restrict__ Wc,
                                             const float* __restrict__ bc,
                                             float* __restrict__ out) {
    if (blockIdx.x < OUT_BLKS) {
        __shared__ float svs[H2];
        __shared__ float zb[HID];
        __shared__ float red[256];
        int t = threadIdx.x;
        svs[t] = d_svec[t];
        __syncthreads();
        // zb GEMV: thread (j = t&127, h = t>>7) sums 128 k's
        {
            int j = t & 127, h = t >> 7;
            float acc = 0.f;
            int k0 = h * 128;
#pragma unroll 8
            for (int k = 0; k < 128; k++)
                acc += svs[k0 + k] * W2[(k0 + k) * HID + j];
            red[t] = acc;
            __syncthreads();
            if (t < HID)
                zb[t] = (red[t] + red[t + 128]) * (1.0f / (float)N_POS) + b2[t];
            __syncthreads();
        }
        // Wc GEMV: thread (c = t&63, seg = t>>6) sums 32 j's
        {
            int cl = t & 63, seg = t >> 6;
            int c = blockIdx.x * 64 + cl;
            float acc = 0.f;
            int j0 = seg * 32;
#pragma unroll 8
            for (int j = 0; j < 32; j++)
                acc += zb[j0 + j] * Wc[(j0 + j) * VOCABSZ + c];
            red[t] = acc;
            __syncthreads();
            if (t < 64)
                out[blockIdx.x * 64 + t] =
                    red[t] + red[t + 64] + red[t + 128] + red[t + 192] + bc[blockIdx.x * 64 + t];
        }
    } else {
        // zero per-frame state for the NEXT replay (invariant: zero on entry)
        int zt = (blockIdx.x - OUT_BLKS) * 256 + threadIdx.x;
        int nz = ZERO_BLKS * 256;
        for (int i = zt; i < N_NODES; i += nz) {
            d_dc[2 * i] = 0; d_dc[2 * i + 1] = 0;
            d_coef[i] = 0.f; d_need[i] = 0; d_sel[i] = 0;
        }
        if (zt == 0) { d_total = 0; d_nneed = 0; }
        if (zt < 8) d_bar[zt] = 0;
    }
}

extern "C" void kernel_launch(void* const* d_in, const int* in_sizes, int n_in,
                              void* d_out, int out_size) {
    const int*   x    = (const int*)d_in[0];
    const int*   ei   = (const int*)d_in[1];
    const int*   pos  = (const int*)d_in[2];
    const float* emb  = (const float*)d_in[3];
    const float* W1   = (const float*)d_in[4];
    const float* b1   = (const float*)d_in[5];
    const float* W2   = (const float*)d_in[6];
    const float* b2   = (const float*)d_in[7];
    const float* Wc   = (const float*)d_in[8];
    const float* bc   = (const float*)d_in[9];
    float* out = (float*)d_out;
    const int* row = ei;
    const int* col = ei + N_EDGES;

    k_build<<<GRID_BUILD, 256>>>(emb, W1, row, col, pos, x, b1);
    k_out<<<OUT_BLKS + ZERO_BLKS, 256>>>(W2, b2, Wc, bc, out);
}